// round 8
// baseline (speedup 1.0000x reference)
#include <cuda_runtime.h>
#include <cuda_fp16.h>
#include <cstdint>

// RandomWalkPE: diag(T^k), k=1..8, T = D^-1 A (A = symmetrized multigraph adjacency),
// then [N,8] @ W_pe[8,16] + b_pe.
//
// Storage fp8 e4m3 scaled x256; gathers accumulate in half2 (HFMA2), 2 rows per block.
// Diagonal extraction (S = T^2; symmetry: M^k[j,i] = deg_i M^k[i,j] invdeg_j):
//   d1 = T[i,i]                                          (CSR, exact)
//   d2 = S[i,i]                                          (fp32 smem acc, k_t2, exact)
//   d3 = deg_i sum_{c in nbr} w_ic S[i,c] invdeg_c       (fp32, k_t2, exact)
//   d4 = deg_i sum_c S[i,c]^2 invdeg_c                   (fp32, k_t2, exact)
//   d5 = deg_i sum_{c in nbr} w_ic T4[i,c] invdeg_c      (k_final, (1,4) split)
//   d6 = deg_i sum_c T3[i,c]^2 invdeg_c                  (k_t3,  (3,3) split)
//   d7 = deg_i sum_c T3[i,c] T4[i,c] invdeg_c            (k_final, (3,4) split)
//   d8 = deg_i sum_c T4[i,c]^2 invdeg_c                  (k_final, (4,4) split)

#define NN   4096
#define NE   65536
#define CAP  128
#define DPE  16
#define FSCALE 256.0f

__device__ int   g_hcol[NN * CAP];
__device__ float g_hw  [NN * CAP];
__device__ __align__(16) int2 g_cw[NN * CAP];   // packed CSR: {col, bits(weight)}
__device__ int   g_nnz [NN];
__device__ float g_deg [NN];
__device__ __align__(16) float g_invdeg[NN];
__device__ float g_wii[NN];
__device__ float g_d2[NN], g_d3[NN], g_d4[NN], g_d6[NN];
__device__ __align__(16) unsigned char g_T2q[(size_t)NN * NN];   // 16 MB, e4m3 x256
__device__ __align__(16) unsigned char g_T3q[(size_t)NN * NN];   // 16 MB, e4m3 x256

// ---------------- K1: init hash tables ----------------
__global__ void k_hinit() {
    int idx = blockIdx.x * blockDim.x + threadIdx.x;
    reinterpret_cast<int4*>(g_hcol)[idx]  = make_int4(-1, -1, -1, -1);
    reinterpret_cast<float4*>(g_hw)[idx]  = make_float4(0.f, 0.f, 0.f, 0.f);
}

// ---------------- K2: hash-insert symmetrized edges ----------------
__device__ __forceinline__ void hins(int r, int c) {
    int base = r * CAP;
    unsigned slot = ((unsigned)c * 2654435761u) >> 25;
    for (;;) {
        int prev = atomicCAS(&g_hcol[base + slot], -1, c);
        if (prev == -1 || prev == c) { atomicAdd(&g_hw[base + slot], 1.0f); return; }
        slot = (slot + 1) & (CAP - 1);
    }
}

__global__ void k_insert(const int* __restrict__ ei) {
    int e = blockIdx.x * blockDim.x + threadIdx.x;
    if (e < NE) {
        int r = ei[e];
        int c = ei[NE + e];
        hins(r, c);
        hins(c, r);
    }
}

// ---------------- K3: compact + normalize ----------------
__global__ void __launch_bounds__(128) k_compact() {
    int i = blockIdx.x, t = threadIdx.x;
    int   col = g_hcol[i * CAP + t];
    float w   = g_hw  [i * CAP + t];
    float v = (col >= 0) ? w : 0.f;

    for (int off = 16; off > 0; off >>= 1) v += __shfl_down_sync(0xffffffffu, v, off);
    __shared__ float red[4];
    if ((t & 31) == 0) red[t >> 5] = v;
    __syncthreads();
    __shared__ float s_inv, s_wii;
    __shared__ int   s_cnt;
    if (t == 0) {
        float d = fmaxf(red[0] + red[1] + red[2] + red[3], 1.0f);
        g_deg[i] = d;
        s_inv = 1.0f / d;
        g_invdeg[i] = s_inv;
        s_cnt = 0; s_wii = 0.f;
    }
    __syncthreads();
    float inv = s_inv;
    if (col >= 0) {
        if (col == i) s_wii = w * inv;
        int p = atomicAdd(&s_cnt, 1);
        g_cw[i * CAP + p] = make_int2(col, __float_as_int(w * inv));
    }
    __syncthreads();
    if (t == 0) { g_nnz[i] = s_cnt; g_wii[i] = s_wii; }
}

// ---------------- helpers ----------------
__device__ __forceinline__ uint2 pack8_fp8_f32(const float* a) {
    unsigned short s0, s1, s2, s3;
    asm("cvt.rn.satfinite.e4m3x2.f32 %0, %1, %2;" : "=h"(s0) : "f"(a[1] * FSCALE), "f"(a[0] * FSCALE));
    asm("cvt.rn.satfinite.e4m3x2.f32 %0, %1, %2;" : "=h"(s1) : "f"(a[3] * FSCALE), "f"(a[2] * FSCALE));
    asm("cvt.rn.satfinite.e4m3x2.f32 %0, %1, %2;" : "=h"(s2) : "f"(a[5] * FSCALE), "f"(a[4] * FSCALE));
    asm("cvt.rn.satfinite.e4m3x2.f32 %0, %1, %2;" : "=h"(s3) : "f"(a[7] * FSCALE), "f"(a[6] * FSCALE));
    uint2 u;
    u.x = (unsigned)s0 | ((unsigned)s1 << 16);
    u.y = (unsigned)s2 | ((unsigned)s3 << 16);
    return u;
}

__device__ __forceinline__ unsigned short h2_to_fp8(__half2 h) {
    unsigned hb = *reinterpret_cast<unsigned*>(&h);
    unsigned short s;
    asm("cvt.rn.satfinite.e4m3x2.f16x2 %0, %1;" : "=h"(s) : "r"(hb));
    return s;
}

__device__ __forceinline__ __half2 fp8_to_h2(unsigned short p) {
    unsigned r;
    asm("cvt.rn.f16x2.e4m3x2 %0, %1;" : "=r"(r) : "h"(p));
    return *reinterpret_cast<__half2*>(&r);
}

__device__ __forceinline__ float warp_red(float v) {
    for (int off = 16; off > 0; off >>= 1) v += __shfl_down_sync(0xffffffffu, v, off);
    return v;
}

// ---------------- K4: S = T*T scatter (fp32 smem), fp8 store, d2/d3/d4 exact --------
__global__ void __launch_bounds__(512) k_t2() {
    int i = blockIdx.x, t = threadIdx.x, wid = t >> 5, lane = t & 31;
    __shared__ float acc[NN];
    __shared__ int   scol[CAP];
    __shared__ float sw[CAP];
    float4* a4 = reinterpret_cast<float4*>(acc);
    float4 z = make_float4(0.f, 0.f, 0.f, 0.f);
    a4[t] = z; a4[t + 512] = z;
    int nn = g_nnz[i];
    if (t < nn) {
        int2 cw = g_cw[i * CAP + t];
        scol[t] = cw.x;
        sw[t]   = __int_as_float(cw.y);
    }
    __syncthreads();
    for (int p = wid; p < nn; p += 16) {
        int   j   = scol[p];
        float wij = sw[p];
        int   nj  = g_nnz[j];
        const int2* jcw = g_cw + j * CAP;
        for (int q = lane; q < nj; q += 32) {
            int2 cw = __ldg(jcw + q);
            atomicAdd(&acc[cw.x], wij * __int_as_float(cw.y));
        }
    }
    __syncthreads();
    int base = 8 * t;
    float av[8];
    #pragma unroll
    for (int k = 0; k < 8; k++) av[k] = acc[base + k];
    reinterpret_cast<uint2*>(g_T2q + (size_t)i * NN)[t] = pack8_fp8_f32(av);

    // d4 = deg * sum_c S[i,c]^2 * invdeg[c]   (exact fp32, reuse av)
    float4 iv0 = *reinterpret_cast<const float4*>(g_invdeg + base);
    float4 iv1 = *reinterpret_cast<const float4*>(g_invdeg + base + 4);
    float iv[8] = {iv0.x, iv0.y, iv0.z, iv0.w, iv1.x, iv1.y, iv1.z, iv1.w};
    float s4 = 0.f;
    #pragma unroll
    for (int k = 0; k < 8; k++) s4 = fmaf(av[k] * iv[k], av[k], s4);

    // d3 = deg * sum_p w_ip * S[i, col_p] * invdeg[col_p]   (exact fp32)
    float s3 = 0.f;
    if (t < nn) {
        int j = scol[t];
        s3 = sw[t] * acc[j] * __ldg(&g_invdeg[j]);
    }

    __shared__ float red[2][16];
    s3 = warp_red(s3); s4 = warp_red(s4);
    if (lane == 0) { red[0][wid] = s3; red[1][wid] = s4; }
    __syncthreads();
    if (t < 2) {
        float x = 0.f;
        for (int q = 0; q < 16; q++) x += red[t][q];
        float d = g_deg[i] * x;
        if (t == 0) g_d3[i] = d; else g_d4[i] = d;
    }
    if (t == 256) g_d2[i] = acc[i];
}

// ------- K5: T3 = T*S (fp8 gather, half2 acc), 2 rows/block, fp8 store, d6 -------
__global__ void __launch_bounds__(512) k_t3() {
    int i0 = blockIdx.x * 2, i1 = i0 + 1;
    int t = threadIdx.x;
    __shared__ unsigned soff[2][CAP];   // j*NN byte offsets
    __shared__ unsigned swh [2][CAP];   // half2 weight bits
    int nn0 = g_nnz[i0], nn1 = g_nnz[i1];
    if (t < CAP) {
        if (t < nn0) {
            int2 cw = g_cw[i0 * CAP + t];
            soff[0][t] = (unsigned)cw.x << 12;
            __half2 h = __float2half2_rn(__int_as_float(cw.y));
            swh[0][t] = *reinterpret_cast<unsigned*>(&h);
        }
    } else if (t < 2 * CAP) {
        int q = t - CAP;
        if (q < nn1) {
            int2 cw = g_cw[i1 * CAP + q];
            soff[1][q] = (unsigned)cw.x << 12;
            __half2 h = __float2half2_rn(__int_as_float(cw.y));
            swh[1][q] = *reinterpret_cast<unsigned*>(&h);
        }
    }
    __syncthreads();

    __half2 zz = __half2half2(__ushort_as_half(0));
    __half2 a0 = zz, a1 = zz, a2 = zz, a3 = zz;   // 256*T3[i0, 8t..]
    __half2 b0 = zz, b1 = zz, b2 = zz, b3 = zz;   // 256*T3[i1, 8t..]
    int nmax = max(nn0, nn1);
    for (int p = 0; p < nmax; p++) {
        if (p < nn0) {
            uint2 v = __ldg(reinterpret_cast<const uint2*>(g_T2q + soff[0][p]) + t);
            unsigned wb = swh[0][p];
            __half2 w2 = *reinterpret_cast<__half2*>(&wb);
            a0 = __hfma2(fp8_to_h2((unsigned short)(v.x & 0xffffu)), w2, a0);
            a1 = __hfma2(fp8_to_h2((unsigned short)(v.x >> 16)),     w2, a1);
            a2 = __hfma2(fp8_to_h2((unsigned short)(v.y & 0xffffu)), w2, a2);
            a3 = __hfma2(fp8_to_h2((unsigned short)(v.y >> 16)),     w2, a3);
        }
        if (p < nn1) {
            uint2 v = __ldg(reinterpret_cast<const uint2*>(g_T2q + soff[1][p]) + t);
            unsigned wb = swh[1][p];
            __half2 w2 = *reinterpret_cast<__half2*>(&wb);
            b0 = __hfma2(fp8_to_h2((unsigned short)(v.x & 0xffffu)), w2, b0);
            b1 = __hfma2(fp8_to_h2((unsigned short)(v.x >> 16)),     w2, b1);
            b2 = __hfma2(fp8_to_h2((unsigned short)(v.y & 0xffffu)), w2, b2);
            b3 = __hfma2(fp8_to_h2((unsigned short)(v.y >> 16)),     w2, b3);
        }
    }
    uint2 u;
    u.x = (unsigned)h2_to_fp8(a0) | ((unsigned)h2_to_fp8(a1) << 16);
    u.y = (unsigned)h2_to_fp8(a2) | ((unsigned)h2_to_fp8(a3) << 16);
    reinterpret_cast<uint2*>(g_T3q + (size_t)i0 * NN)[t] = u;
    u.x = (unsigned)h2_to_fp8(b0) | ((unsigned)h2_to_fp8(b1) << 16);
    u.y = (unsigned)h2_to_fp8(b2) | ((unsigned)h2_to_fp8(b3) << 16);
    reinterpret_cast<uint2*>(g_T3q + (size_t)i1 * NN)[t] = u;

    // d6 for both rows
    int base = 8 * t;
    float4 iv0 = *reinterpret_cast<const float4*>(g_invdeg + base);
    float4 iv1 = *reinterpret_cast<const float4*>(g_invdeg + base + 4);
    float iv[8] = {iv0.x, iv0.y, iv0.z, iv0.w, iv1.x, iv1.y, iv1.z, iv1.w};
    float2 fa0 = __half22float2(a0), fa1 = __half22float2(a1);
    float2 fa2 = __half22float2(a2), fa3 = __half22float2(a3);
    float2 fb0 = __half22float2(b0), fb1 = __half22float2(b1);
    float2 fb2 = __half22float2(b2), fb3 = __half22float2(b3);
    float afA[8] = {fa0.x, fa0.y, fa1.x, fa1.y, fa2.x, fa2.y, fa3.x, fa3.y};
    float afB[8] = {fb0.x, fb0.y, fb1.x, fb1.y, fb2.x, fb2.y, fb3.x, fb3.y};
    float s6a = 0.f, s6b = 0.f;
    #pragma unroll
    for (int k = 0; k < 8; k++) {
        s6a = fmaf(afA[k] * iv[k], afA[k], s6a);
        s6b = fmaf(afB[k] * iv[k], afB[k], s6b);
    }
    __shared__ float red[2][16];
    s6a = warp_red(s6a); s6b = warp_red(s6b);
    int wid = t >> 5, lane = t & 31;
    if (lane == 0) { red[0][wid] = s6a; red[1][wid] = s6b; }
    __syncthreads();
    if (t < 2) {
        float x = 0.f;
        for (int q = 0; q < 16; q++) x += red[t][q];
        int i = (t == 0) ? i0 : i1;
        g_d6[i] = g_deg[i] * x * (1.0f / (FSCALE * FSCALE));
    }
}

// ------- K6: T4 rows (fp8 gather, half2 acc), 2 rows/block + d5/d7/d8 + projection ---
__global__ void __launch_bounds__(512) k_final(const float* __restrict__ W,
                                               const float* __restrict__ b,
                                               float* __restrict__ out) {
    int i0 = blockIdx.x * 2, i1 = i0 + 1;
    int t = threadIdx.x;
    __shared__ unsigned soff[2][CAP];
    __shared__ unsigned swh [2][CAP];
    __shared__ float    swf [2][CAP];   // fp32 weights for d5
    int nn0 = g_nnz[i0], nn1 = g_nnz[i1];
    if (t < CAP) {
        if (t < nn0) {
            int2 cw = g_cw[i0 * CAP + t];
            soff[0][t] = (unsigned)cw.x << 12;
            float wf = __int_as_float(cw.y);
            swf[0][t] = wf;
            __half2 h = __float2half2_rn(wf);
            swh[0][t] = *reinterpret_cast<unsigned*>(&h);
        }
    } else if (t < 2 * CAP) {
        int q = t - CAP;
        if (q < nn1) {
            int2 cw = g_cw[i1 * CAP + q];
            soff[1][q] = (unsigned)cw.x << 12;
            float wf = __int_as_float(cw.y);
            swf[1][q] = wf;
            __half2 h = __float2half2_rn(wf);
            swh[1][q] = *reinterpret_cast<unsigned*>(&h);
        }
    }
    __syncthreads();

    __half2 zz = __half2half2(__ushort_as_half(0));
    __half2 a0 = zz, a1 = zz, a2 = zz, a3 = zz;   // 256*T4[i0, 8t..]
    __half2 b0 = zz, b1 = zz, b2 = zz, b3 = zz;   // 256*T4[i1, 8t..]
    int nmax = max(nn0, nn1);
    for (int p = 0; p < nmax; p++) {
        if (p < nn0) {
            uint2 v = __ldg(reinterpret_cast<const uint2*>(g_T3q + soff[0][p]) + t);
            unsigned wb = swh[0][p];
            __half2 w2 = *reinterpret_cast<__half2*>(&wb);
            a0 = __hfma2(fp8_to_h2((unsigned short)(v.x & 0xffffu)), w2, a0);
            a1 = __hfma2(fp8_to_h2((unsigned short)(v.x >> 16)),     w2, a1);
            a2 = __hfma2(fp8_to_h2((unsigned short)(v.y & 0xffffu)), w2, a2);
            a3 = __hfma2(fp8_to_h2((unsigned short)(v.y >> 16)),     w2, a3);
        }
        if (p < nn1) {
            uint2 v = __ldg(reinterpret_cast<const uint2*>(g_T3q + soff[1][p]) + t);
            unsigned wb = swh[1][p];
            __half2 w2 = *reinterpret_cast<__half2*>(&wb);
            b0 = __hfma2(fp8_to_h2((unsigned short)(v.x & 0xffffu)), w2, b0);
            b1 = __hfma2(fp8_to_h2((unsigned short)(v.x >> 16)),     w2, b1);
            b2 = __hfma2(fp8_to_h2((unsigned short)(v.y & 0xffffu)), w2, b2);
            b3 = __hfma2(fp8_to_h2((unsigned short)(v.y >> 16)),     w2, b3);
        }
    }
    float2 fa0 = __half22float2(a0), fa1 = __half22float2(a1);
    float2 fa2 = __half22float2(a2), fa3 = __half22float2(a3);
    float2 fb0 = __half22float2(b0), fb1 = __half22float2(b1);
    float2 fb2 = __half22float2(b2), fb3 = __half22float2(b3);
    float afA[8] = {fa0.x, fa0.y, fa1.x, fa1.y, fa2.x, fa2.y, fa3.x, fa3.y};
    float afB[8] = {fb0.x, fb0.y, fb1.x, fb1.y, fb2.x, fb2.y, fb3.x, fb3.y};

    // own T3 rows (fp8, x256)
    uint2 ovA = __ldg(reinterpret_cast<const uint2*>(g_T3q + (size_t)i0 * NN) + t);
    uint2 ovB = __ldg(reinterpret_cast<const uint2*>(g_T3q + (size_t)i1 * NN) + t);
    float2 oa0 = __half22float2(fp8_to_h2((unsigned short)(ovA.x & 0xffffu)));
    float2 oa1 = __half22float2(fp8_to_h2((unsigned short)(ovA.x >> 16)));
    float2 oa2 = __half22float2(fp8_to_h2((unsigned short)(ovA.y & 0xffffu)));
    float2 oa3 = __half22float2(fp8_to_h2((unsigned short)(ovA.y >> 16)));
    float2 ob0 = __half22float2(fp8_to_h2((unsigned short)(ovB.x & 0xffffu)));
    float2 ob1 = __half22float2(fp8_to_h2((unsigned short)(ovB.x >> 16)));
    float2 ob2 = __half22float2(fp8_to_h2((unsigned short)(ovB.y & 0xffffu)));
    float2 ob3 = __half22float2(fp8_to_h2((unsigned short)(ovB.y >> 16)));
    float t3A[8] = {oa0.x, oa0.y, oa1.x, oa1.y, oa2.x, oa2.y, oa3.x, oa3.y};
    float t3B[8] = {ob0.x, ob0.y, ob1.x, ob1.y, ob2.x, ob2.y, ob3.x, ob3.y};

    int base = 8 * t;
    float4 iv0 = *reinterpret_cast<const float4*>(g_invdeg + base);
    float4 iv1 = *reinterpret_cast<const float4*>(g_invdeg + base + 4);
    float iv[8] = {iv0.x, iv0.y, iv0.z, iv0.w, iv1.x, iv1.y, iv1.z, iv1.w};
    float s7a = 0.f, s8a = 0.f, s7b = 0.f, s8b = 0.f;
    #pragma unroll
    for (int k = 0; k < 8; k++) {
        float waA = afA[k] * iv[k];
        float waB = afB[k] * iv[k];
        s7a = fmaf(t3A[k], waA, s7a);
        s8a = fmaf(afA[k], waA, s8a);
        s7b = fmaf(t3B[k], waB, s7b);
        s8b = fmaf(afB[k], waB, s8b);
    }
    // d5 sparse (1,4) split per row
    float s5a = 0.f, s5b = 0.f;
    for (int p = 0; p < nn0; p++) {
        int j = (int)(soff[0][p] >> 12);
        if ((j >> 3) == t) s5a += swf[0][p] * afA[j & 7] * iv[j & 7];
    }
    for (int p = 0; p < nn1; p++) {
        int j = (int)(soff[1][p] >> 12);
        if ((j >> 3) == t) s5b += swf[1][p] * afB[j & 7] * iv[j & 7];
    }

    __shared__ float red[6][16];
    s5a = warp_red(s5a); s7a = warp_red(s7a); s8a = warp_red(s8a);
    s5b = warp_red(s5b); s7b = warp_red(s7b); s8b = warp_red(s8b);
    int wid = t >> 5, lane = t & 31;
    if (lane == 0) {
        red[0][wid] = s5a; red[1][wid] = s7a; red[2][wid] = s8a;
        red[3][wid] = s5b; red[4][wid] = s7b; red[5][wid] = s8b;
    }
    __syncthreads();
    __shared__ float S[6];
    if (t < 6) {
        float x = 0.f;
        for (int q = 0; q < 16; q++) x += red[t][q];
        S[t] = x;
    }
    __syncthreads();

    if (t < 2 * DPE) {
        int r  = t >> 4;             // 0 -> i0, 1 -> i1
        int c  = t & 15;
        int i  = (r == 0) ? i0 : i1;
        const float* Sr = S + 3 * r;
        float deg = g_deg[i];
        float d1 = g_wii[i];
        float d2 = g_d2[i], d3 = g_d3[i], d4 = g_d4[i], d6 = g_d6[i];
        float d5 = deg * Sr[0] * (1.0f / FSCALE);
        float d7 = deg * Sr[1] * (1.0f / (FSCALE * FSCALE));
        float d8 = deg * Sr[2] * (1.0f / (FSCALE * FSCALE));
        float o = b[c];
        o = fmaf(d1, W[0 * DPE + c], o);
        o = fmaf(d2, W[1 * DPE + c], o);
        o = fmaf(d3, W[2 * DPE + c], o);
        o = fmaf(d4, W[3 * DPE + c], o);
        o = fmaf(d5, W[4 * DPE + c], o);
        o = fmaf(d6, W[5 * DPE + c], o);
        o = fmaf(d7, W[6 * DPE + c], o);
        o = fmaf(d8, W[7 * DPE + c], o);
        out[i * DPE + c] = o;
    }
}

extern "C" void kernel_launch(void* const* d_in, const int* in_sizes, int n_in,
                              void* d_out, int out_size) {
    const int*   edge = nullptr;
    const float* W    = nullptr;
    const float* bias = nullptr;
    for (int k = 0; k < n_in; k++) {
        if (in_sizes[k] == 2 * NE)       edge = (const int*)d_in[k];
        else if (in_sizes[k] == 8 * DPE) W    = (const float*)d_in[k];
        else if (in_sizes[k] == DPE)     bias = (const float*)d_in[k];
    }
    float* out = (float*)d_out;

    k_hinit  <<<(NN * CAP / 4) / 256, 256>>>();
    k_insert <<<(NE + 255) / 256, 256>>>(edge);
    k_compact<<<NN, 128>>>();
    k_t2     <<<NN, 512>>>();
    k_t3     <<<NN / 2, 512>>>();
    k_final  <<<NN / 2, 512>>>(W, bias, out);
}

// round 9
// speedup vs baseline: 1.1316x; 1.1316x over previous
#include <cuda_runtime.h>
#include <cuda_fp16.h>
#include <cstdint>

// RandomWalkPE: diag(T^k), k=1..8, T = D^-1 A (A = symmetrized multigraph adjacency),
// then [N,8] @ W_pe[8,16] + b_pe.
//
// Storage fp8 e4m3 scaled x256; gathers accumulate in half2 (HFMA2), 1 row per block.
// Diagonal extraction (S = T^2; symmetry: M^k[j,i] = deg_i M^k[i,j] invdeg_j):
//   d1 = T[i,i]                                          (CSR, exact)
//   d2 = S[i,i]                                          (fp32 smem acc, k_t2, exact)
//   d3 = deg_i sum_{c in nbr} w_ic S[i,c] invdeg_c       (fp32, k_t2, exact)
//   d4 = deg_i sum_c S[i,c]^2 invdeg_c                   (fp32, k_t2, exact)
//   d5 = deg_i sum_{c in nbr} w_ic T4[i,c] invdeg_c      (k_final, (1,4) split)
//   d6 = deg_i sum_c T3[i,c]^2 invdeg_c                  (k_t3,  (3,3) split)
//   d7 = deg_i sum_c T3[i,c] T4[i,c] invdeg_c            (k_final, (3,4) split)
//   d8 = deg_i sum_c T4[i,c]^2 invdeg_c                  (k_final, (4,4) split)

#define NN   4096
#define NE   65536
#define CAP  128
#define DPE  16
#define FSCALE 256.0f

__device__ int   g_hcol[NN * CAP];
__device__ float g_hw  [NN * CAP];
__device__ __align__(16) int2 g_cw[NN * CAP];   // packed CSR: {col, bits(weight)}
__device__ int   g_nnz [NN];
__device__ float g_deg [NN];
__device__ __align__(16) float g_invdeg[NN];
__device__ float g_wii[NN];
__device__ float g_d2[NN], g_d3[NN], g_d4[NN], g_d6[NN];
__device__ __align__(16) unsigned char g_T2q[(size_t)NN * NN];   // 16 MB, e4m3 x256
__device__ __align__(16) unsigned char g_T3q[(size_t)NN * NN];   // 16 MB, e4m3 x256

// ---------------- K1: init hash tables ----------------
__global__ void k_hinit() {
    int idx = blockIdx.x * blockDim.x + threadIdx.x;
    reinterpret_cast<int4*>(g_hcol)[idx]  = make_int4(-1, -1, -1, -1);
    reinterpret_cast<float4*>(g_hw)[idx]  = make_float4(0.f, 0.f, 0.f, 0.f);
}

// ---------------- K2: hash-insert symmetrized edges ----------------
__device__ __forceinline__ void hins(int r, int c) {
    int base = r * CAP;
    unsigned slot = ((unsigned)c * 2654435761u) >> 25;
    for (;;) {
        int prev = atomicCAS(&g_hcol[base + slot], -1, c);
        if (prev == -1 || prev == c) { atomicAdd(&g_hw[base + slot], 1.0f); return; }
        slot = (slot + 1) & (CAP - 1);
    }
}

__global__ void k_insert(const int* __restrict__ ei) {
    int e = blockIdx.x * blockDim.x + threadIdx.x;
    if (e < NE) {
        int r = ei[e];
        int c = ei[NE + e];
        hins(r, c);
        hins(c, r);
    }
}

// ---------------- K3: compact + normalize ----------------
__global__ void __launch_bounds__(128) k_compact() {
    int i = blockIdx.x, t = threadIdx.x;
    int   col = g_hcol[i * CAP + t];
    float w   = g_hw  [i * CAP + t];
    float v = (col >= 0) ? w : 0.f;

    for (int off = 16; off > 0; off >>= 1) v += __shfl_down_sync(0xffffffffu, v, off);
    __shared__ float red[4];
    if ((t & 31) == 0) red[t >> 5] = v;
    __syncthreads();
    __shared__ float s_inv, s_wii;
    __shared__ int   s_cnt;
    if (t == 0) {
        float d = fmaxf(red[0] + red[1] + red[2] + red[3], 1.0f);
        g_deg[i] = d;
        s_inv = 1.0f / d;
        g_invdeg[i] = s_inv;
        s_cnt = 0; s_wii = 0.f;
    }
    __syncthreads();
    float inv = s_inv;
    if (col >= 0) {
        if (col == i) s_wii = w * inv;
        int p = atomicAdd(&s_cnt, 1);
        g_cw[i * CAP + p] = make_int2(col, __float_as_int(w * inv));
    }
    __syncthreads();
    if (t == 0) { g_nnz[i] = s_cnt; g_wii[i] = s_wii; }
}

// ---------------- helpers ----------------
__device__ __forceinline__ uint2 pack8_fp8_f32(const float* a) {
    unsigned short s0, s1, s2, s3;
    asm("cvt.rn.satfinite.e4m3x2.f32 %0, %1, %2;" : "=h"(s0) : "f"(a[1] * FSCALE), "f"(a[0] * FSCALE));
    asm("cvt.rn.satfinite.e4m3x2.f32 %0, %1, %2;" : "=h"(s1) : "f"(a[3] * FSCALE), "f"(a[2] * FSCALE));
    asm("cvt.rn.satfinite.e4m3x2.f32 %0, %1, %2;" : "=h"(s2) : "f"(a[5] * FSCALE), "f"(a[4] * FSCALE));
    asm("cvt.rn.satfinite.e4m3x2.f32 %0, %1, %2;" : "=h"(s3) : "f"(a[7] * FSCALE), "f"(a[6] * FSCALE));
    uint2 u;
    u.x = (unsigned)s0 | ((unsigned)s1 << 16);
    u.y = (unsigned)s2 | ((unsigned)s3 << 16);
    return u;
}

__device__ __forceinline__ unsigned short h2_to_fp8(__half2 h) {
    unsigned hb = *reinterpret_cast<unsigned*>(&h);
    unsigned short s;
    asm("cvt.rn.satfinite.e4m3x2.f16x2 %0, %1;" : "=h"(s) : "r"(hb));
    return s;
}

__device__ __forceinline__ __half2 fp8_to_h2(unsigned short p) {
    unsigned r;
    asm("cvt.rn.f16x2.e4m3x2 %0, %1;" : "=r"(r) : "h"(p));
    return *reinterpret_cast<__half2*>(&r);
}

__device__ __forceinline__ float warp_red(float v) {
    for (int off = 16; off > 0; off >>= 1) v += __shfl_down_sync(0xffffffffu, v, off);
    return v;
}

// ---------------- K4: S = T*T scatter (fp32 smem), fp8 store, d2/d3/d4 exact --------
__global__ void __launch_bounds__(512) k_t2() {
    int i = blockIdx.x, t = threadIdx.x, wid = t >> 5, lane = t & 31;
    __shared__ float acc[NN];
    __shared__ int   scol[CAP];
    __shared__ float sw[CAP];
    float4* a4 = reinterpret_cast<float4*>(acc);
    float4 z = make_float4(0.f, 0.f, 0.f, 0.f);
    a4[t] = z; a4[t + 512] = z;
    int nn = g_nnz[i];
    if (t < nn) {
        int2 cw = g_cw[i * CAP + t];
        scol[t] = cw.x;
        sw[t]   = __int_as_float(cw.y);
    }
    __syncthreads();
    for (int p = wid; p < nn; p += 16) {
        int   j   = scol[p];
        float wij = sw[p];
        int   nj  = g_nnz[j];
        const int2* jcw = g_cw + j * CAP;
        for (int q = lane; q < nj; q += 32) {
            int2 cw = __ldg(jcw + q);
            atomicAdd(&acc[cw.x], wij * __int_as_float(cw.y));
        }
    }
    __syncthreads();
    int base = 8 * t;
    float av[8];
    #pragma unroll
    for (int k = 0; k < 8; k++) av[k] = acc[base + k];
    reinterpret_cast<uint2*>(g_T2q + (size_t)i * NN)[t] = pack8_fp8_f32(av);

    // d4 = deg * sum_c S[i,c]^2 * invdeg[c]   (exact fp32, reuse av)
    float4 iv0 = *reinterpret_cast<const float4*>(g_invdeg + base);
    float4 iv1 = *reinterpret_cast<const float4*>(g_invdeg + base + 4);
    float iv[8] = {iv0.x, iv0.y, iv0.z, iv0.w, iv1.x, iv1.y, iv1.z, iv1.w};
    float s4 = 0.f;
    #pragma unroll
    for (int k = 0; k < 8; k++) s4 = fmaf(av[k] * iv[k], av[k], s4);

    // d3 = deg * sum_p w_ip * S[i, col_p] * invdeg[col_p]   (exact fp32)
    float s3 = 0.f;
    if (t < nn) {
        int j = scol[t];
        s3 = sw[t] * acc[j] * __ldg(&g_invdeg[j]);
    }

    __shared__ float red[2][16];
    s3 = warp_red(s3); s4 = warp_red(s4);
    if (lane == 0) { red[0][wid] = s3; red[1][wid] = s4; }
    __syncthreads();
    if (t < 2) {
        float x = 0.f;
        for (int q = 0; q < 16; q++) x += red[t][q];
        float d = g_deg[i] * x;
        if (t == 0) g_d3[i] = d; else g_d4[i] = d;
    }
    if (t == 256) g_d2[i] = acc[i];
}

// ------- K5: T3 = T*S (fp8 gather, half2 acc), fp8 store, d6 -------
__global__ void __launch_bounds__(512) k_t3() {
    int i = blockIdx.x, t = threadIdx.x;
    __shared__ unsigned soff[CAP];   // precomputed col*NN byte offsets
    __shared__ unsigned swh [CAP];   // pre-converted half2 weight bits
    int nn = g_nnz[i];
    if (t < nn) {
        int2 cw = g_cw[i * CAP + t];
        soff[t] = (unsigned)cw.x << 12;
        __half2 h = __float2half2_rn(__int_as_float(cw.y));
        swh[t] = *reinterpret_cast<unsigned*>(&h);
    }
    __syncthreads();
    __half2 zz = __half2half2(__ushort_as_half(0));
    __half2 c0 = zz, c1 = zz, c2 = zz, c3 = zz;   // 256*T3[i, 8t..8t+7]
    for (int p = 0; p < nn; p++) {
        uint2 v = __ldg(reinterpret_cast<const uint2*>(g_T2q + soff[p]) + t);
        unsigned wb = swh[p];
        __half2 w2 = *reinterpret_cast<__half2*>(&wb);
        c0 = __hfma2(fp8_to_h2((unsigned short)(v.x & 0xffffu)), w2, c0);
        c1 = __hfma2(fp8_to_h2((unsigned short)(v.x >> 16)),     w2, c1);
        c2 = __hfma2(fp8_to_h2((unsigned short)(v.y & 0xffffu)), w2, c2);
        c3 = __hfma2(fp8_to_h2((unsigned short)(v.y >> 16)),     w2, c3);
    }
    // store fp8 (values already x256 scaled)
    uint2 u;
    u.x = (unsigned)h2_to_fp8(c0) | ((unsigned)h2_to_fp8(c1) << 16);
    u.y = (unsigned)h2_to_fp8(c2) | ((unsigned)h2_to_fp8(c3) << 16);
    reinterpret_cast<uint2*>(g_T3q + (size_t)i * NN)[t] = u;

    // d6 = deg/FSCALE^2 * sum_c a[c]^2 * invdeg[c]
    float2 f0 = __half22float2(c0), f1 = __half22float2(c1);
    float2 f2 = __half22float2(c2), f3 = __half22float2(c3);
    float af[8] = {f0.x, f0.y, f1.x, f1.y, f2.x, f2.y, f3.x, f3.y};
    int base = 8 * t;
    float4 iv0 = *reinterpret_cast<const float4*>(g_invdeg + base);
    float4 iv1 = *reinterpret_cast<const float4*>(g_invdeg + base + 4);
    float iv[8] = {iv0.x, iv0.y, iv0.z, iv0.w, iv1.x, iv1.y, iv1.z, iv1.w};
    float s6 = 0.f;
    #pragma unroll
    for (int k = 0; k < 8; k++) s6 = fmaf(af[k] * iv[k], af[k], s6);

    __shared__ float red[16];
    s6 = warp_red(s6);
    int wid = t >> 5, lane = t & 31;
    if (lane == 0) red[wid] = s6;
    __syncthreads();
    if (t == 0) {
        float x = 0.f;
        for (int q = 0; q < 16; q++) x += red[q];
        g_d6[i] = g_deg[i] * x * (1.0f / (FSCALE * FSCALE));
    }
}

// ------- K6: T4 row (fp8 gather, half2 acc) + d5, d7, d8 + projection -------
__global__ void __launch_bounds__(512) k_final(const float* __restrict__ W,
                                               const float* __restrict__ b,
                                               float* __restrict__ out) {
    int i = blockIdx.x, t = threadIdx.x;
    __shared__ unsigned soff[CAP];
    __shared__ unsigned swh [CAP];
    __shared__ float    swf [CAP];   // fp32 weights for d5
    int nn = g_nnz[i];
    if (t < nn) {
        int2 cw = g_cw[i * CAP + t];
        soff[t] = (unsigned)cw.x << 12;
        float wf = __int_as_float(cw.y);
        swf[t] = wf;
        __half2 h = __float2half2_rn(wf);
        swh[t] = *reinterpret_cast<unsigned*>(&h);
    }
    __syncthreads();
    __half2 zz = __half2half2(__ushort_as_half(0));
    __half2 c0 = zz, c1 = zz, c2 = zz, c3 = zz;   // 256*T4[i, 8t..8t+7]
    for (int p = 0; p < nn; p++) {
        uint2 v = __ldg(reinterpret_cast<const uint2*>(g_T3q + soff[p]) + t);
        unsigned wb = swh[p];
        __half2 w2 = *reinterpret_cast<__half2*>(&wb);
        c0 = __hfma2(fp8_to_h2((unsigned short)(v.x & 0xffffu)), w2, c0);
        c1 = __hfma2(fp8_to_h2((unsigned short)(v.x >> 16)),     w2, c1);
        c2 = __hfma2(fp8_to_h2((unsigned short)(v.y & 0xffffu)), w2, c2);
        c3 = __hfma2(fp8_to_h2((unsigned short)(v.y >> 16)),     w2, c3);
    }
    float2 f0 = __half22float2(c0), f1 = __half22float2(c1);
    float2 f2 = __half22float2(c2), f3 = __half22float2(c3);
    float af[8] = {f0.x, f0.y, f1.x, f1.y, f2.x, f2.y, f3.x, f3.y};

    // own T3 row (fp8, x256)
    uint2 ov = __ldg(reinterpret_cast<const uint2*>(g_T3q + (size_t)i * NN) + t);
    float2 o0 = __half22float2(fp8_to_h2((unsigned short)(ov.x & 0xffffu)));
    float2 o1 = __half22float2(fp8_to_h2((unsigned short)(ov.x >> 16)));
    float2 o2 = __half22float2(fp8_to_h2((unsigned short)(ov.y & 0xffffu)));
    float2 o3 = __half22float2(fp8_to_h2((unsigned short)(ov.y >> 16)));
    float t3o[8] = {o0.x, o0.y, o1.x, o1.y, o2.x, o2.y, o3.x, o3.y};

    int base = 8 * t;
    float4 iv0 = *reinterpret_cast<const float4*>(g_invdeg + base);
    float4 iv1 = *reinterpret_cast<const float4*>(g_invdeg + base + 4);
    float iv[8] = {iv0.x, iv0.y, iv0.z, iv0.w, iv1.x, iv1.y, iv1.z, iv1.w};
    float s7 = 0.f, s8 = 0.f;
    #pragma unroll
    for (int k = 0; k < 8; k++) {
        float wa = af[k] * iv[k];
        s7 = fmaf(t3o[k], wa, s7);
        s8 = fmaf(af[k],  wa, s8);
    }
    // d5 sparse (1,4) split: sum over neighbors p with col owned by this thread
    float s5 = 0.f;
    for (int p = 0; p < nn; p++) {
        int j = (int)(soff[p] >> 12);
        if ((j >> 3) == t) s5 += swf[p] * af[j & 7] * iv[j & 7];
    }

    __shared__ float red[3][16];
    s5 = warp_red(s5); s7 = warp_red(s7); s8 = warp_red(s8);
    int wid = t >> 5, lane = t & 31;
    if (lane == 0) { red[0][wid] = s5; red[1][wid] = s7; red[2][wid] = s8; }
    __syncthreads();
    __shared__ float S[3];
    if (t < 3) {
        float x = 0.f;
        for (int q = 0; q < 16; q++) x += red[t][q];
        S[t] = x;
    }
    __syncthreads();

    if (t < DPE) {
        float deg = g_deg[i];
        float d1 = g_wii[i];
        float d2 = g_d2[i], d3 = g_d3[i], d4 = g_d4[i], d6 = g_d6[i];
        float d5 = deg * S[0] * (1.0f / FSCALE);
        float d7 = deg * S[1] * (1.0f / (FSCALE * FSCALE));
        float d8 = deg * S[2] * (1.0f / (FSCALE * FSCALE));
        float o = b[t];
        o = fmaf(d1, W[0 * DPE + t], o);
        o = fmaf(d2, W[1 * DPE + t], o);
        o = fmaf(d3, W[2 * DPE + t], o);
        o = fmaf(d4, W[3 * DPE + t], o);
        o = fmaf(d5, W[4 * DPE + t], o);
        o = fmaf(d6, W[5 * DPE + t], o);
        o = fmaf(d7, W[6 * DPE + t], o);
        o = fmaf(d8, W[7 * DPE + t], o);
        out[i * DPE + t] = o;
    }
}

extern "C" void kernel_launch(void* const* d_in, const int* in_sizes, int n_in,
                              void* d_out, int out_size) {
    const int*   edge = nullptr;
    const float* W    = nullptr;
    const float* bias = nullptr;
    for (int k = 0; k < n_in; k++) {
        if (in_sizes[k] == 2 * NE)       edge = (const int*)d_in[k];
        else if (in_sizes[k] == 8 * DPE) W    = (const float*)d_in[k];
        else if (in_sizes[k] == DPE)     bias = (const float*)d_in[k];
    }
    float* out = (float*)d_out;

    k_hinit  <<<(NN * CAP / 4) / 256, 256>>>();
    k_insert <<<(NE + 255) / 256, 256>>>(edge);
    k_compact<<<NN, 128>>>();
    k_t2     <<<NN, 512>>>();
    k_t3     <<<NN, 512>>>();
    k_final  <<<NN, 512>>>(W, bias, out);
}

// round 11
// speedup vs baseline: 1.1538x; 1.0196x over previous
#include <cuda_runtime.h>
#include <cuda_fp16.h>
#include <cstdint>

// RandomWalkPE: diag(T^k), k=1..8, T = D^-1 A (A = symmetrized multigraph adjacency),
// then [N,8] @ W_pe[8,16] + b_pe.
//
// Storage fp8 e4m3 scaled x256; gathers accumulate in half2 (HFMA2),
// 256 threads/row, uint4 (16 cols) per thread.
// Diagonal extraction (S = T^2; symmetry: M^k[j,i] = deg_i M^k[i,j] invdeg_j):
//   d1 = T[i,i]                                          (CSR, exact)
//   d2 = S[i,i]                                          (fp32 smem acc, k_t2, exact)
//   d3 = deg_i sum_{c in nbr} w_ic S[i,c] invdeg_c       (fp32, k_t2, exact)
//   d4 = deg_i sum_c S[i,c]^2 invdeg_c                   (fp32, k_t2, exact)
//   d5 = deg_i sum_{c in nbr} w_ic T4[i,c] invdeg_c      (k_final, (1,4) split)
//   d6 = deg_i sum_c T3[i,c]^2 invdeg_c                  (k_t3,  (3,3) split)
//   d7 = deg_i sum_c T3[i,c] T4[i,c] invdeg_c            (k_final, (3,4) split)
//   d8 = deg_i sum_c T4[i,c]^2 invdeg_c                  (k_final, (4,4) split)

#define NN   4096
#define NE   65536
#define CAP  128
#define DPE  16
#define FSCALE 256.0f

__device__ int   g_hcol[NN * CAP];
__device__ float g_hw  [NN * CAP];
__device__ __align__(16) int2 g_cw[NN * CAP];   // packed CSR: {col, bits(weight)}
__device__ int   g_nnz [NN];
__device__ float g_deg [NN];
__device__ __align__(16) float g_invdeg[NN];
__device__ float g_wii[NN];
__device__ float g_d2[NN], g_d3[NN], g_d4[NN], g_d6[NN];
__device__ __align__(16) unsigned char g_T2q[(size_t)NN * NN];   // 16 MB, e4m3 x256
__device__ __align__(16) unsigned char g_T3q[(size_t)NN * NN];   // 16 MB, e4m3 x256

// ---------------- K1: init hash tables ----------------
__global__ void k_hinit() {
    int idx = blockIdx.x * blockDim.x + threadIdx.x;
    reinterpret_cast<int4*>(g_hcol)[idx]  = make_int4(-1, -1, -1, -1);
    reinterpret_cast<float4*>(g_hw)[idx]  = make_float4(0.f, 0.f, 0.f, 0.f);
}

// ---------------- K2: hash-insert symmetrized edges ----------------
__device__ __forceinline__ void hins(int r, int c) {
    int base = r * CAP;
    unsigned slot = ((unsigned)c * 2654435761u) >> 25;
    for (;;) {
        int prev = atomicCAS(&g_hcol[base + slot], -1, c);
        if (prev == -1 || prev == c) { atomicAdd(&g_hw[base + slot], 1.0f); return; }
        slot = (slot + 1) & (CAP - 1);
    }
}

__global__ void k_insert(const int* __restrict__ ei) {
    int e = blockIdx.x * blockDim.x + threadIdx.x;
    if (e < NE) {
        int r = ei[e];
        int c = ei[NE + e];
        hins(r, c);
        hins(c, r);
    }
}

// ---------------- K3: compact + normalize ----------------
__global__ void __launch_bounds__(128) k_compact() {
    int i = blockIdx.x, t = threadIdx.x;
    int   col = g_hcol[i * CAP + t];
    float w   = g_hw  [i * CAP + t];
    float v = (col >= 0) ? w : 0.f;

    for (int off = 16; off > 0; off >>= 1) v += __shfl_down_sync(0xffffffffu, v, off);
    __shared__ float red[4];
    if ((t & 31) == 0) red[t >> 5] = v;
    __syncthreads();
    __shared__ float s_inv, s_wii;
    __shared__ int   s_cnt;
    if (t == 0) {
        float d = fmaxf(red[0] + red[1] + red[2] + red[3], 1.0f);
        g_deg[i] = d;
        s_inv = 1.0f / d;
        g_invdeg[i] = s_inv;
        s_cnt = 0; s_wii = 0.f;
    }
    __syncthreads();
    float inv = s_inv;
    if (col >= 0) {
        if (col == i) s_wii = w * inv;
        int p = atomicAdd(&s_cnt, 1);
        g_cw[i * CAP + p] = make_int2(col, __float_as_int(w * inv));
    }
    __syncthreads();
    if (t == 0) { g_nnz[i] = s_cnt; g_wii[i] = s_wii; }
}

// ---------------- helpers ----------------
__device__ __forceinline__ uint2 pack8_fp8_f32(const float* a) {
    unsigned short s0, s1, s2, s3;
    asm("cvt.rn.satfinite.e4m3x2.f32 %0, %1, %2;" : "=h"(s0) : "f"(a[1] * FSCALE), "f"(a[0] * FSCALE));
    asm("cvt.rn.satfinite.e4m3x2.f32 %0, %1, %2;" : "=h"(s1) : "f"(a[3] * FSCALE), "f"(a[2] * FSCALE));
    asm("cvt.rn.satfinite.e4m3x2.f32 %0, %1, %2;" : "=h"(s2) : "f"(a[5] * FSCALE), "f"(a[4] * FSCALE));
    asm("cvt.rn.satfinite.e4m3x2.f32 %0, %1, %2;" : "=h"(s3) : "f"(a[7] * FSCALE), "f"(a[6] * FSCALE));
    uint2 u;
    u.x = (unsigned)s0 | ((unsigned)s1 << 16);
    u.y = (unsigned)s2 | ((unsigned)s3 << 16);
    return u;
}

__device__ __forceinline__ unsigned short h2_to_fp8(__half2 h) {
    unsigned hb = *reinterpret_cast<unsigned*>(&h);
    unsigned short s;
    asm("cvt.rn.satfinite.e4m3x2.f16x2 %0, %1;" : "=h"(s) : "r"(hb));
    return s;
}

__device__ __forceinline__ __half2 fp8_to_h2(unsigned short p) {
    unsigned r;
    asm("cvt.rn.f16x2.e4m3x2 %0, %1;" : "=r"(r) : "h"(p));
    return *reinterpret_cast<__half2*>(&r);
}

__device__ __forceinline__ float warp_red(float v) {
    for (int off = 16; off > 0; off >>= 1) v += __shfl_down_sync(0xffffffffu, v, off);
    return v;
}

// accumulate 16 fp8 cols (one uint4) into 8 half2 accumulators
__device__ __forceinline__ void fma16(uint4 v, __half2 w2, __half2* c) {
    c[0] = __hfma2(fp8_to_h2((unsigned short)(v.x & 0xffffu)), w2, c[0]);
    c[1] = __hfma2(fp8_to_h2((unsigned short)(v.x >> 16)),     w2, c[1]);
    c[2] = __hfma2(fp8_to_h2((unsigned short)(v.y & 0xffffu)), w2, c[2]);
    c[3] = __hfma2(fp8_to_h2((unsigned short)(v.y >> 16)),     w2, c[3]);
    c[4] = __hfma2(fp8_to_h2((unsigned short)(v.z & 0xffffu)), w2, c[4]);
    c[5] = __hfma2(fp8_to_h2((unsigned short)(v.z >> 16)),     w2, c[5]);
    c[6] = __hfma2(fp8_to_h2((unsigned short)(v.w & 0xffffu)), w2, c[6]);
    c[7] = __hfma2(fp8_to_h2((unsigned short)(v.w >> 16)),     w2, c[7]);
}

__device__ __forceinline__ void h2x8_to_f16(const __half2* c, float* f) {
    #pragma unroll
    for (int k = 0; k < 8; k++) {
        float2 fk = __half22float2(c[k]);
        f[2 * k] = fk.x; f[2 * k + 1] = fk.y;
    }
}

__device__ __forceinline__ uint4 pack16_fp8(const __half2* c) {
    uint4 u;
    u.x = (unsigned)h2_to_fp8(c[0]) | ((unsigned)h2_to_fp8(c[1]) << 16);
    u.y = (unsigned)h2_to_fp8(c[2]) | ((unsigned)h2_to_fp8(c[3]) << 16);
    u.z = (unsigned)h2_to_fp8(c[4]) | ((unsigned)h2_to_fp8(c[5]) << 16);
    u.w = (unsigned)h2_to_fp8(c[6]) | ((unsigned)h2_to_fp8(c[7]) << 16);
    return u;
}

__device__ __forceinline__ void load_iv16(int base, float* iv) {
    float4 v0 = *reinterpret_cast<const float4*>(g_invdeg + base);
    float4 v1 = *reinterpret_cast<const float4*>(g_invdeg + base + 4);
    float4 v2 = *reinterpret_cast<const float4*>(g_invdeg + base + 8);
    float4 v3 = *reinterpret_cast<const float4*>(g_invdeg + base + 12);
    iv[0]=v0.x; iv[1]=v0.y; iv[2]=v0.z; iv[3]=v0.w;
    iv[4]=v1.x; iv[5]=v1.y; iv[6]=v1.z; iv[7]=v1.w;
    iv[8]=v2.x; iv[9]=v2.y; iv[10]=v2.z; iv[11]=v2.w;
    iv[12]=v3.x; iv[13]=v3.y; iv[14]=v3.z; iv[15]=v3.w;
}

// ---------------- K4: S = T*T scatter (fp32 smem), fp8 store, d2/d3/d4 exact --------
__global__ void __launch_bounds__(512) k_t2() {
    int i = blockIdx.x, t = threadIdx.x, wid = t >> 5, lane = t & 31;
    __shared__ float acc[NN];
    __shared__ int   scol[CAP];
    __shared__ float sw[CAP];
    __shared__ int   snj[CAP];          // staged g_nnz[col] (breaks serial chain)
    float4* a4 = reinterpret_cast<float4*>(acc);
    float4 z = make_float4(0.f, 0.f, 0.f, 0.f);
    a4[t] = z; a4[t + 512] = z;
    int nn = g_nnz[i];
    if (t < nn) {
        int2 cw = g_cw[i * CAP + t];
        scol[t] = cw.x;
        sw[t]   = __int_as_float(cw.y);
        snj[t]  = g_nnz[cw.x];
    }
    __syncthreads();
    for (int p = wid; p < nn; p += 16) {
        int   j   = scol[p];
        float wij = sw[p];
        int   nj  = snj[p];
        const int2* jcw = g_cw + j * CAP;
        for (int q = lane; q < nj; q += 32) {
            int2 cw = __ldg(jcw + q);
            atomicAdd(&acc[cw.x], wij * __int_as_float(cw.y));
        }
    }
    __syncthreads();
    int base = 8 * t;
    float av[8];
    #pragma unroll
    for (int k = 0; k < 8; k++) av[k] = acc[base + k];
    reinterpret_cast<uint2*>(g_T2q + (size_t)i * NN)[t] = pack8_fp8_f32(av);

    // d4 = deg * sum_c S[i,c]^2 * invdeg[c]   (exact fp32, reuse av)
    float4 iv0 = *reinterpret_cast<const float4*>(g_invdeg + base);
    float4 iv1 = *reinterpret_cast<const float4*>(g_invdeg + base + 4);
    float iv[8] = {iv0.x, iv0.y, iv0.z, iv0.w, iv1.x, iv1.y, iv1.z, iv1.w};
    float s4 = 0.f;
    #pragma unroll
    for (int k = 0; k < 8; k++) s4 = fmaf(av[k] * iv[k], av[k], s4);

    // d3 = deg * sum_p w_ip * S[i, col_p] * invdeg[col_p]   (exact fp32)
    float s3 = 0.f;
    if (t < nn) {
        int j = scol[t];
        s3 = sw[t] * acc[j] * __ldg(&g_invdeg[j]);
    }

    __shared__ float red[2][16];
    s3 = warp_red(s3); s4 = warp_red(s4);
    if (lane == 0) { red[0][wid] = s3; red[1][wid] = s4; }
    __syncthreads();
    if (t < 2) {
        float x = 0.f;
        for (int q = 0; q < 16; q++) x += red[t][q];
        float d = g_deg[i] * x;
        if (t == 0) g_d3[i] = d; else g_d4[i] = d;
    }
    if (t == 256) g_d2[i] = acc[i];
}

// ------- K5: T3 = T*S (fp8 uint4 gather, half2 acc), fp8 store, d6 -------
__global__ void __launch_bounds__(256) k_t3() {
    int i = blockIdx.x, t = threadIdx.x;       // t owns cols 16t..16t+15
    __shared__ unsigned soff[CAP];             // precomputed col*NN byte offsets
    __shared__ unsigned swh [CAP];             // pre-converted half2 weight bits
    int nn = g_nnz[i];
    if (t < nn) {
        int2 cw = g_cw[i * CAP + t];
        soff[t] = (unsigned)cw.x << 12;
        __half2 h = __float2half2_rn(__int_as_float(cw.y));
        swh[t] = *reinterpret_cast<unsigned*>(&h);
    }
    __syncthreads();
    __half2 c[8];
    #pragma unroll
    for (int k = 0; k < 8; k++) c[k] = __half2half2(__ushort_as_half(0));
    for (int p = 0; p < nn; p++) {
        uint4 v = __ldg(reinterpret_cast<const uint4*>(g_T2q + soff[p]) + t);
        unsigned wb = swh[p];
        fma16(v, *reinterpret_cast<__half2*>(&wb), c);
    }
    reinterpret_cast<uint4*>(g_T3q + (size_t)i * NN)[t] = pack16_fp8(c);

    // d6 = deg/FSCALE^2 * sum_c a[c]^2 * invdeg[c]
    float af[16], iv[16];
    h2x8_to_f16(c, af);
    load_iv16(16 * t, iv);
    float s6 = 0.f;
    #pragma unroll
    for (int k = 0; k < 16; k++) s6 = fmaf(af[k] * iv[k], af[k], s6);

    __shared__ float red[8];
    s6 = warp_red(s6);
    int wid = t >> 5, lane = t & 31;
    if (lane == 0) red[wid] = s6;
    __syncthreads();
    if (t == 0) {
        float x = 0.f;
        for (int q = 0; q < 8; q++) x += red[q];
        g_d6[i] = g_deg[i] * x * (1.0f / (FSCALE * FSCALE));
    }
}

// ------- K6: T4 row (fp8 uint4 gather, half2 acc) + d5, d7, d8 + projection -------
__global__ void __launch_bounds__(256) k_final(const float* __restrict__ W,
                                               const float* __restrict__ b,
                                               float* __restrict__ out) {
    int i = blockIdx.x, t = threadIdx.x;       // t owns cols 16t..16t+15
    __shared__ unsigned soff[CAP];
    __shared__ unsigned swh [CAP];
    __shared__ float    swf [CAP];             // fp32 weights for d5
    int nn = g_nnz[i];
    if (t < nn) {
        int2 cw = g_cw[i * CAP + t];
        soff[t] = (unsigned)cw.x << 12;
        float wf = __int_as_float(cw.y);
        swf[t] = wf;
        __half2 h = __float2half2_rn(wf);
        swh[t] = *reinterpret_cast<unsigned*>(&h);
    }
    __syncthreads();
    __half2 c[8];
    #pragma unroll
    for (int k = 0; k < 8; k++) c[k] = __half2half2(__ushort_as_half(0));
    for (int p = 0; p < nn; p++) {
        uint4 v = __ldg(reinterpret_cast<const uint4*>(g_T3q + soff[p]) + t);
        unsigned wb = swh[p];
        fma16(v, *reinterpret_cast<__half2*>(&wb), c);
    }
    float af[16], iv[16];
    h2x8_to_f16(c, af);
    load_iv16(16 * t, iv);

    // own T3 row (fp8, x256)
    uint4 ov = __ldg(reinterpret_cast<const uint4*>(g_T3q + (size_t)i * NN) + t);
    __half2 oc[8];
    oc[0] = fp8_to_h2((unsigned short)(ov.x & 0xffffu));
    oc[1] = fp8_to_h2((unsigned short)(ov.x >> 16));
    oc[2] = fp8_to_h2((unsigned short)(ov.y & 0xffffu));
    oc[3] = fp8_to_h2((unsigned short)(ov.y >> 16));
    oc[4] = fp8_to_h2((unsigned short)(ov.z & 0xffffu));
    oc[5] = fp8_to_h2((unsigned short)(ov.z >> 16));
    oc[6] = fp8_to_h2((unsigned short)(ov.w & 0xffffu));
    oc[7] = fp8_to_h2((unsigned short)(ov.w >> 16));
    float t3o[16];
    h2x8_to_f16(oc, t3o);

    float s7 = 0.f, s8 = 0.f;
    #pragma unroll
    for (int k = 0; k < 16; k++) {
        float wa = af[k] * iv[k];
        s7 = fmaf(t3o[k], wa, s7);
        s8 = fmaf(af[k],  wa, s8);
    }
    // d5 sparse (1,4) split: neighbors whose col falls in this thread's 16-col span
    float s5 = 0.f;
    for (int p = 0; p < nn; p++) {
        int j = (int)(soff[p] >> 12);
        if ((j >> 4) == t) s5 += swf[p] * af[j & 15] * iv[j & 15];
    }

    __shared__ float red[3][8];
    s5 = warp_red(s5); s7 = warp_red(s7); s8 = warp_red(s8);
    int wid = t >> 5, lane = t & 31;
    if (lane == 0) { red[0][wid] = s5; red[1][wid] = s7; red[2][wid] = s8; }
    __syncthreads();
    __shared__ float S[3];
    if (t < 3) {
        float x = 0.f;
        for (int q = 0; q < 8; q++) x += red[t][q];
        S[t] = x;
    }
    __syncthreads();

    if (t < DPE) {
        float deg = g_deg[i];
        float d1 = g_wii[i];
        float d2 = g_d2[i], d3 = g_d3[i], d4 = g_d4[i], d6 = g_d6[i];
        float d5 = deg * S[0] * (1.0f / FSCALE);
        float d7 = deg * S[1] * (1.0f / (FSCALE * FSCALE));
        float d8 = deg * S[2] * (1.0f / (FSCALE * FSCALE));
        float o = b[t];
        o = fmaf(d1, W[0 * DPE + t], o);
        o = fmaf(d2, W[1 * DPE + t], o);
        o = fmaf(d3, W[2 * DPE + t], o);
        o = fmaf(d4, W[3 * DPE + t], o);
        o = fmaf(d5, W[4 * DPE + t], o);
        o = fmaf(d6, W[5 * DPE + t], o);
        o = fmaf(d7, W[6 * DPE + t], o);
        o = fmaf(d8, W[7 * DPE + t], o);
        out[i * DPE + t] = o;
    }
}

extern "C" void kernel_launch(void* const* d_in, const int* in_sizes, int n_in,
                              void* d_out, int out_size) {
    const int*   edge = nullptr;
    const float* W    = nullptr;
    const float* bias = nullptr;
    for (int k = 0; k < n_in; k++) {
        if (in_sizes[k] == 2 * NE)       edge = (const int*)d_in[k];
        else if (in_sizes[k] == 8 * DPE) W    = (const float*)d_in[k];
        else if (in_sizes[k] == DPE)     bias = (const float*)d_in[k];
    }
    float* out = (float*)d_out;

    k_hinit  <<<(NN * CAP / 4) / 256, 256>>>();
    k_insert <<<(NE + 255) / 256, 256>>>(edge);
    k_compact<<<NN, 128>>>();
    k_t2     <<<NN, 512>>>();
    k_t3     <<<NN, 256>>>();
    k_final  <<<NN, 256>>>(W, bias, out);
}

// round 12
// speedup vs baseline: 1.3420x; 1.1631x over previous
#include <cuda_runtime.h>
#include <cuda_fp16.h>
#include <cstdint>

// RandomWalkPE: diag(T^k), k=1..8, T = D^-1 A (A = symmetrized multigraph adjacency),
// then [N,8] @ W_pe[8,16] + b_pe.
//
// Storage fp8 e4m3 scaled x256; gathers accumulate in half2 (HFMA2),
// 256 threads/row, uint4 (16 cols) per thread.
// Diagonal extraction (S = T^2; symmetry: M^k[j,i] = deg_i M^k[i,j] invdeg_j):
//   d1 = T[i,i]                                          (CSR, exact)
//   d2 = S[i,i]                                          (fp32 smem acc, k_t2, exact)
//   d3 = deg_i sum_{c in nbr} w_ic S[i,c] invdeg_c       (fp32, k_t2, exact)
//   d4 = deg_i sum_c S[i,c]^2 invdeg_c                   (fp32, k_t2, exact)
//   d5 = deg_i sum_c S[i,c] T3[i,c] invdeg_c             (k_t3,  (2,3) split)
//   d6 = deg_i sum_c T3[i,c]^2 invdeg_c                  (k_t3,  (3,3) split)
//   d7 = deg_i sum_c T3[i,c] T4[i,c] invdeg_c            (k_final, (3,4) split)
//   d8 = deg_i sum_c T4[i,c]^2 invdeg_c                  (k_final, (4,4) split)

#define NN   4096
#define NE   65536
#define CAP  128
#define DPE  16
#define FSCALE 256.0f

__device__ int   g_hcol[NN * CAP];
__device__ float g_hw  [NN * CAP];
__device__ __align__(16) int2 g_cw[NN * CAP];   // packed CSR: {col, bits(weight)}
__device__ int   g_nnz [NN];
__device__ float g_deg [NN];
__device__ __align__(16) float g_invdeg[NN];
__device__ float g_wii[NN];
__device__ float g_d2[NN], g_d3[NN], g_d4[NN], g_d5[NN], g_d6[NN];
__device__ __align__(16) unsigned char g_T2q[(size_t)NN * NN];   // 16 MB, e4m3 x256
__device__ __align__(16) unsigned char g_T3q[(size_t)NN * NN];   // 16 MB, e4m3 x256

// ---------------- K1: init hash tables ----------------
__global__ void k_hinit() {
    int idx = blockIdx.x * blockDim.x + threadIdx.x;
    reinterpret_cast<int4*>(g_hcol)[idx]  = make_int4(-1, -1, -1, -1);
    reinterpret_cast<float4*>(g_hw)[idx]  = make_float4(0.f, 0.f, 0.f, 0.f);
}

// ---------------- K2: hash-insert symmetrized edges ----------------
__device__ __forceinline__ void hins(int r, int c) {
    int base = r * CAP;
    unsigned slot = ((unsigned)c * 2654435761u) >> 25;
    for (;;) {
        int prev = atomicCAS(&g_hcol[base + slot], -1, c);
        if (prev == -1 || prev == c) { atomicAdd(&g_hw[base + slot], 1.0f); return; }
        slot = (slot + 1) & (CAP - 1);
    }
}

__global__ void k_insert(const int* __restrict__ ei) {
    int e = blockIdx.x * blockDim.x + threadIdx.x;
    if (e < NE) {
        int r = ei[e];
        int c = ei[NE + e];
        hins(r, c);
        hins(c, r);
    }
}

// ---------------- K3: compact + normalize ----------------
__global__ void __launch_bounds__(128) k_compact() {
    int i = blockIdx.x, t = threadIdx.x;
    int   col = g_hcol[i * CAP + t];
    float w   = g_hw  [i * CAP + t];
    float v = (col >= 0) ? w : 0.f;

    for (int off = 16; off > 0; off >>= 1) v += __shfl_down_sync(0xffffffffu, v, off);
    __shared__ float red[4];
    if ((t & 31) == 0) red[t >> 5] = v;
    __syncthreads();
    __shared__ float s_inv, s_wii;
    __shared__ int   s_cnt;
    if (t == 0) {
        float d = fmaxf(red[0] + red[1] + red[2] + red[3], 1.0f);
        g_deg[i] = d;
        s_inv = 1.0f / d;
        g_invdeg[i] = s_inv;
        s_cnt = 0; s_wii = 0.f;
    }
    __syncthreads();
    float inv = s_inv;
    if (col >= 0) {
        if (col == i) s_wii = w * inv;
        int p = atomicAdd(&s_cnt, 1);
        g_cw[i * CAP + p] = make_int2(col, __float_as_int(w * inv));
    }
    __syncthreads();
    if (t == 0) { g_nnz[i] = s_cnt; g_wii[i] = s_wii; }
}

// ---------------- helpers ----------------
__device__ __forceinline__ uint2 pack8_fp8_f32(const float* a) {
    unsigned short s0, s1, s2, s3;
    asm("cvt.rn.satfinite.e4m3x2.f32 %0, %1, %2;" : "=h"(s0) : "f"(a[1] * FSCALE), "f"(a[0] * FSCALE));
    asm("cvt.rn.satfinite.e4m3x2.f32 %0, %1, %2;" : "=h"(s1) : "f"(a[3] * FSCALE), "f"(a[2] * FSCALE));
    asm("cvt.rn.satfinite.e4m3x2.f32 %0, %1, %2;" : "=h"(s2) : "f"(a[5] * FSCALE), "f"(a[4] * FSCALE));
    asm("cvt.rn.satfinite.e4m3x2.f32 %0, %1, %2;" : "=h"(s3) : "f"(a[7] * FSCALE), "f"(a[6] * FSCALE));
    uint2 u;
    u.x = (unsigned)s0 | ((unsigned)s1 << 16);
    u.y = (unsigned)s2 | ((unsigned)s3 << 16);
    return u;
}

__device__ __forceinline__ unsigned short h2_to_fp8(__half2 h) {
    unsigned hb = *reinterpret_cast<unsigned*>(&h);
    unsigned short s;
    asm("cvt.rn.satfinite.e4m3x2.f16x2 %0, %1;" : "=h"(s) : "r"(hb));
    return s;
}

__device__ __forceinline__ __half2 fp8_to_h2(unsigned short p) {
    unsigned r;
    asm("cvt.rn.f16x2.e4m3x2 %0, %1;" : "=r"(r) : "h"(p));
    return *reinterpret_cast<__half2*>(&r);
}

__device__ __forceinline__ float warp_red(float v) {
    for (int off = 16; off > 0; off >>= 1) v += __shfl_down_sync(0xffffffffu, v, off);
    return v;
}

// accumulate 16 fp8 cols (one uint4) into 8 half2 accumulators
__device__ __forceinline__ void fma16(uint4 v, __half2 w2, __half2* c) {
    c[0] = __hfma2(fp8_to_h2((unsigned short)(v.x & 0xffffu)), w2, c[0]);
    c[1] = __hfma2(fp8_to_h2((unsigned short)(v.x >> 16)),     w2, c[1]);
    c[2] = __hfma2(fp8_to_h2((unsigned short)(v.y & 0xffffu)), w2, c[2]);
    c[3] = __hfma2(fp8_to_h2((unsigned short)(v.y >> 16)),     w2, c[3]);
    c[4] = __hfma2(fp8_to_h2((unsigned short)(v.z & 0xffffu)), w2, c[4]);
    c[5] = __hfma2(fp8_to_h2((unsigned short)(v.z >> 16)),     w2, c[5]);
    c[6] = __hfma2(fp8_to_h2((unsigned short)(v.w & 0xffffu)), w2, c[6]);
    c[7] = __hfma2(fp8_to_h2((unsigned short)(v.w >> 16)),     w2, c[7]);
}

__device__ __forceinline__ void h2x8_to_f16(const __half2* c, float* f) {
    #pragma unroll
    for (int k = 0; k < 8; k++) {
        float2 fk = __half22float2(c[k]);
        f[2 * k] = fk.x; f[2 * k + 1] = fk.y;
    }
}

__device__ __forceinline__ void unpack16_fp8(uint4 v, float* f) {
    __half2 oc[8];
    oc[0] = fp8_to_h2((unsigned short)(v.x & 0xffffu));
    oc[1] = fp8_to_h2((unsigned short)(v.x >> 16));
    oc[2] = fp8_to_h2((unsigned short)(v.y & 0xffffu));
    oc[3] = fp8_to_h2((unsigned short)(v.y >> 16));
    oc[4] = fp8_to_h2((unsigned short)(v.z & 0xffffu));
    oc[5] = fp8_to_h2((unsigned short)(v.z >> 16));
    oc[6] = fp8_to_h2((unsigned short)(v.w & 0xffffu));
    oc[7] = fp8_to_h2((unsigned short)(v.w >> 16));
    h2x8_to_f16(oc, f);
}

__device__ __forceinline__ uint4 pack16_fp8(const __half2* c) {
    uint4 u;
    u.x = (unsigned)h2_to_fp8(c[0]) | ((unsigned)h2_to_fp8(c[1]) << 16);
    u.y = (unsigned)h2_to_fp8(c[2]) | ((unsigned)h2_to_fp8(c[3]) << 16);
    u.z = (unsigned)h2_to_fp8(c[4]) | ((unsigned)h2_to_fp8(c[5]) << 16);
    u.w = (unsigned)h2_to_fp8(c[6]) | ((unsigned)h2_to_fp8(c[7]) << 16);
    return u;
}

__device__ __forceinline__ void load_iv16(int base, float* iv) {
    float4 v0 = *reinterpret_cast<const float4*>(g_invdeg + base);
    float4 v1 = *reinterpret_cast<const float4*>(g_invdeg + base + 4);
    float4 v2 = *reinterpret_cast<const float4*>(g_invdeg + base + 8);
    float4 v3 = *reinterpret_cast<const float4*>(g_invdeg + base + 12);
    iv[0]=v0.x; iv[1]=v0.y; iv[2]=v0.z; iv[3]=v0.w;
    iv[4]=v1.x; iv[5]=v1.y; iv[6]=v1.z; iv[7]=v1.w;
    iv[8]=v2.x; iv[9]=v2.y; iv[10]=v2.z; iv[11]=v2.w;
    iv[12]=v3.x; iv[13]=v3.y; iv[14]=v3.z; iv[15]=v3.w;
}

// ---------------- K4: S = T*T scatter (fp32 smem), fp8 store, d2/d3/d4 exact --------
__global__ void __launch_bounds__(512) k_t2() {
    int i = blockIdx.x, t = threadIdx.x, wid = t >> 5, lane = t & 31;
    __shared__ float acc[NN];
    __shared__ int   scol[CAP];
    __shared__ float sw[CAP];
    __shared__ int   snj[CAP];          // staged g_nnz[col]
    float4* a4 = reinterpret_cast<float4*>(acc);
    float4 z = make_float4(0.f, 0.f, 0.f, 0.f);
    a4[t] = z; a4[t + 512] = z;
    int nn = g_nnz[i];
    if (t < nn) {
        int2 cw = g_cw[i * CAP + t];
        scol[t] = cw.x;
        sw[t]   = __int_as_float(cw.y);
        snj[t]  = g_nnz[cw.x];
    }
    __syncthreads();
    for (int p = wid; p < nn; p += 16) {
        int   j   = scol[p];
        float wij = sw[p];
        int   nj  = snj[p];
        const int4* jcw4 = reinterpret_cast<const int4*>(g_cw + j * CAP);
        for (int q = lane; 2 * q < nj; q += 32) {   // paired int4 loads: entries 2q, 2q+1
            int4 cw2 = __ldg(jcw4 + q);
            atomicAdd(&acc[cw2.x], wij * __int_as_float(cw2.y));
            if (2 * q + 1 < nj)
                atomicAdd(&acc[cw2.z], wij * __int_as_float(cw2.w));
        }
    }
    __syncthreads();
    int base = 8 * t;
    float av[8];
    #pragma unroll
    for (int k = 0; k < 8; k++) av[k] = acc[base + k];
    reinterpret_cast<uint2*>(g_T2q + (size_t)i * NN)[t] = pack8_fp8_f32(av);

    // d4 = deg * sum_c S[i,c]^2 * invdeg[c]   (exact fp32, reuse av)
    float4 iv0 = *reinterpret_cast<const float4*>(g_invdeg + base);
    float4 iv1 = *reinterpret_cast<const float4*>(g_invdeg + base + 4);
    float iv[8] = {iv0.x, iv0.y, iv0.z, iv0.w, iv1.x, iv1.y, iv1.z, iv1.w};
    float s4 = 0.f;
    #pragma unroll
    for (int k = 0; k < 8; k++) s4 = fmaf(av[k] * iv[k], av[k], s4);

    // d3 = deg * sum_p w_ip * S[i, col_p] * invdeg[col_p]   (exact fp32)
    float s3 = 0.f;
    if (t < nn) {
        int j = scol[t];
        s3 = sw[t] * acc[j] * __ldg(&g_invdeg[j]);
    }

    __shared__ float red[2][16];
    s3 = warp_red(s3); s4 = warp_red(s4);
    if (lane == 0) { red[0][wid] = s3; red[1][wid] = s4; }
    __syncthreads();
    if (t < 2) {
        float x = 0.f;
        for (int q = 0; q < 16; q++) x += red[t][q];
        float d = g_deg[i] * x;
        if (t == 0) g_d3[i] = d; else g_d4[i] = d;
    }
    if (t == 256) g_d2[i] = acc[i];
}

// ------- K5: T3 = T*S (fp8 uint4 gather, half2 acc), fp8 store, d5 + d6 -------
__global__ void __launch_bounds__(256) k_t3() {
    int i = blockIdx.x, t = threadIdx.x;       // t owns cols 16t..16t+15
    __shared__ unsigned soff[CAP];             // precomputed col*NN byte offsets
    __shared__ unsigned swh [CAP];             // pre-converted half2 weight bits
    int nn = g_nnz[i];
    if (t < nn) {
        int2 cw = g_cw[i * CAP + t];
        soff[t] = (unsigned)cw.x << 12;
        __half2 h = __float2half2_rn(__int_as_float(cw.y));
        swh[t] = *reinterpret_cast<unsigned*>(&h);
    }
    __syncthreads();
    __half2 c[8];
    #pragma unroll
    for (int k = 0; k < 8; k++) c[k] = __half2half2(__ushort_as_half(0));
    for (int p = 0; p < nn; p++) {
        uint4 v = __ldg(reinterpret_cast<const uint4*>(g_T2q + soff[p]) + t);
        unsigned wb = swh[p];
        fma16(v, *reinterpret_cast<__half2*>(&wb), c);
    }
    reinterpret_cast<uint4*>(g_T3q + (size_t)i * NN)[t] = pack16_fp8(c);

    // own S row (x256) for d5 = (2,3) split
    uint4 sv = __ldg(reinterpret_cast<const uint4*>(g_T2q + (size_t)i * NN) + t);
    float s16[16];
    unpack16_fp8(sv, s16);

    float af[16], iv[16];
    h2x8_to_f16(c, af);
    load_iv16(16 * t, iv);
    float s5 = 0.f, s6 = 0.f;
    #pragma unroll
    for (int k = 0; k < 16; k++) {
        float wa = af[k] * iv[k];
        s5 = fmaf(s16[k], wa, s5);
        s6 = fmaf(af[k],  wa, s6);
    }

    __shared__ float red[2][8];
    s5 = warp_red(s5); s6 = warp_red(s6);
    int wid = t >> 5, lane = t & 31;
    if (lane == 0) { red[0][wid] = s5; red[1][wid] = s6; }
    __syncthreads();
    if (t < 2) {
        float x = 0.f;
        for (int q = 0; q < 8; q++) x += red[t][q];
        float d = g_deg[i] * x * (1.0f / (FSCALE * FSCALE));
        if (t == 0) g_d5[i] = d; else g_d6[i] = d;
    }
}

// ------- K6: T4 row (fp8 uint4 gather, half2 acc) + d7, d8 + projection -------
__global__ void __launch_bounds__(256) k_final(const float* __restrict__ W,
                                               const float* __restrict__ b,
                                               float* __restrict__ out) {
    int i = blockIdx.x, t = threadIdx.x;       // t owns cols 16t..16t+15
    __shared__ unsigned soff[CAP];
    __shared__ unsigned swh [CAP];
    int nn = g_nnz[i];
    if (t < nn) {
        int2 cw = g_cw[i * CAP + t];
        soff[t] = (unsigned)cw.x << 12;
        __half2 h = __float2half2_rn(__int_as_float(cw.y));
        swh[t] = *reinterpret_cast<unsigned*>(&h);
    }
    __syncthreads();
    __half2 c[8];
    #pragma unroll
    for (int k = 0; k < 8; k++) c[k] = __half2half2(__ushort_as_half(0));
    for (int p = 0; p < nn; p++) {
        uint4 v = __ldg(reinterpret_cast<const uint4*>(g_T3q + soff[p]) + t);
        unsigned wb = swh[p];
        fma16(v, *reinterpret_cast<__half2*>(&wb), c);
    }
    float af[16], iv[16];
    h2x8_to_f16(c, af);
    load_iv16(16 * t, iv);

    // own T3 row (fp8, x256)
    uint4 ov = __ldg(reinterpret_cast<const uint4*>(g_T3q + (size_t)i * NN) + t);
    float t3o[16];
    unpack16_fp8(ov, t3o);

    float s7 = 0.f, s8 = 0.f;
    #pragma unroll
    for (int k = 0; k < 16; k++) {
        float wa = af[k] * iv[k];
        s7 = fmaf(t3o[k], wa, s7);
        s8 = fmaf(af[k],  wa, s8);
    }

    __shared__ float red[2][8];
    s7 = warp_red(s7); s8 = warp_red(s8);
    int wid = t >> 5, lane = t & 31;
    if (lane == 0) { red[0][wid] = s7; red[1][wid] = s8; }
    __syncthreads();
    __shared__ float S[2];
    if (t < 2) {
        float x = 0.f;
        for (int q = 0; q < 8; q++) x += red[t][q];
        S[t] = x;
    }
    __syncthreads();

    if (t < DPE) {
        float deg = g_deg[i];
        float d1 = g_wii[i];
        float d2 = g_d2[i], d3 = g_d3[i], d4 = g_d4[i];
        float d5 = g_d5[i], d6 = g_d6[i];
        float d7 = deg * S[0] * (1.0f / (FSCALE * FSCALE));
        float d8 = deg * S[1] * (1.0f / (FSCALE * FSCALE));
        float o = b[t];
        o = fmaf(d1, W[0 * DPE + t], o);
        o = fmaf(d2, W[1 * DPE + t], o);
        o = fmaf(d3, W[2 * DPE + t], o);
        o = fmaf(d4, W[3 * DPE + t], o);
        o = fmaf(d5, W[4 * DPE + t], o);
        o = fmaf(d6, W[5 * DPE + t], o);
        o = fmaf(d7, W[6 * DPE + t], o);
        o = fmaf(d8, W[7 * DPE + t], o);
        out[i * DPE + t] = o;
    }
}

extern "C" void kernel_launch(void* const* d_in, const int* in_sizes, int n_in,
                              void* d_out, int out_size) {
    const int*   edge = nullptr;
    const float* W    = nullptr;
    const float* bias = nullptr;
    for (int k = 0; k < n_in; k++) {
        if (in_sizes[k] == 2 * NE)       edge = (const int*)d_in[k];
        else if (in_sizes[k] == 8 * DPE) W    = (const float*)d_in[k];
        else if (in_sizes[k] == DPE)     bias = (const float*)d_in[k];
    }
    float* out = (float*)d_out;

    k_hinit  <<<(NN * CAP / 4) / 256, 256>>>();
    k_insert <<<(NE + 255) / 256, 256>>>(edge);
    k_compact<<<NN, 128>>>();
    k_t2     <<<NN, 512>>>();
    k_t3     <<<NN, 256>>>();
    k_final  <<<NN, 256>>>(W, bias, out);
}